// round 14
// baseline (speedup 1.0000x reference)
#include <cuda_runtime.h>
#include <cuda_bf16.h>
#include <cstdint>

// CenterLoss: out = mean_i ||x_i - centers[labels_i]||^2
// (clamp [1e-12,1e12] dropped: per-row dist ~2D~4096, clamp effect <1e-12/B.)
//
// R13: ONE kernel, zero aux launches. R5's validated streaming core
// (quarter-row units, 4x LDG.128 x-stream + 4x LDG.128 c-gather, 5 CTAs/SM)
// + per-CTA label-dtype probe (warp-0 ballot over first 32 odd words)
// + last-block finalize (device accumulator, self-cleaning for graph replay).
// R12 proved L2 traffic is NOT binding (bf16 c: -0.45us main, +2.9us convert);
// the ~5.8 TB/s DRAM-effective ceiling is the wall, so we reclaim aux time.

#define THREADS 256
#define CTAS_PER_SM 5
#define NBLOCKS (148 * CTAS_PER_SM)

__device__ float        g_acc = 0.0f;
__device__ unsigned int g_cnt = 0u;

template <int VPR>   // float4s per row; VPR==0 -> generic (runtime vpr, guarded)
__global__ __launch_bounds__(THREADS, CTAS_PER_SM)
void center_loss_fused(const float4* __restrict__ x4,
                       const unsigned int* __restrict__ labw,
                       const float4* __restrict__ c4,
                       float* __restrict__ out,
                       int nunits, int rvpr, float inv_B) {
    const int tid    = threadIdx.x;
    const int lane   = tid & 31;
    const int warp   = blockIdx.x * (THREADS / 32) + (tid >> 5);
    const int nwarps = gridDim.x * (THREADS / 32);
    const int vpr    = (VPR > 0) ? VPR : rvpr;
    const int vq     = vpr >> 2;

    // ---- per-CTA label dtype probe (warp 0) ----
    // int64 labels (< C): every odd 32-bit word is 0.
    // int32 labels uniform in [0,C): P(first 32 odd words all 0) ~ C^-32 ~ 0.
    __shared__ int s_is64;
    if (tid < 32) {
        unsigned w = labw[2 * tid + 1];
        unsigned any = __ballot_sync(0xffffffffu, w != 0u);
        if (tid == 0) s_is64 = (any == 0u) ? 1 : 0;
    }
    __syncthreads();
    const int lsh = s_is64;

    float a0 = 0.f, a1 = 0.f, a2 = 0.f, a3 = 0.f;

    for (int u = warp; u < nunits; u += nwarps) {
        const int row = u >> 2;                // 4 quarter-units per row
        const int q   = u & 3;
        const int lab = (int)labw[(unsigned)row << lsh];

        const float4* __restrict__ xp = x4 + (size_t)row * vpr + q * vq + lane;
        const float4* __restrict__ cp = c4 + (size_t)lab * vpr + q * vq + lane;

        if (VPR == 512) {                      // fast path: unguarded
            float4 xv0 = __ldcs(xp);
            float4 xv1 = __ldcs(xp + 32);
            float4 xv2 = __ldcs(xp + 64);
            float4 xv3 = __ldcs(xp + 96);
            float4 cv0 = __ldg(cp);
            float4 cv1 = __ldg(cp + 32);
            float4 cv2 = __ldg(cp + 64);
            float4 cv3 = __ldg(cp + 96);
            float d;
            d = xv0.x - cv0.x; a0 = fmaf(d, d, a0);
            d = xv0.y - cv0.y; a1 = fmaf(d, d, a1);
            d = xv0.z - cv0.z; a2 = fmaf(d, d, a2);
            d = xv0.w - cv0.w; a3 = fmaf(d, d, a3);
            d = xv1.x - cv1.x; a0 = fmaf(d, d, a0);
            d = xv1.y - cv1.y; a1 = fmaf(d, d, a1);
            d = xv1.z - cv1.z; a2 = fmaf(d, d, a2);
            d = xv1.w - cv1.w; a3 = fmaf(d, d, a3);
            d = xv2.x - cv2.x; a0 = fmaf(d, d, a0);
            d = xv2.y - cv2.y; a1 = fmaf(d, d, a1);
            d = xv2.z - cv2.z; a2 = fmaf(d, d, a2);
            d = xv2.w - cv2.w; a3 = fmaf(d, d, a3);
            d = xv3.x - cv3.x; a0 = fmaf(d, d, a0);
            d = xv3.y - cv3.y; a1 = fmaf(d, d, a1);
            d = xv3.z - cv3.z; a2 = fmaf(d, d, a2);
            d = xv3.w - cv3.w; a3 = fmaf(d, d, a3);
        } else {                               // generic: guarded
            #pragma unroll
            for (int k = 0; k < 4; k++) {
                if (q * vq + lane + 32 * k >= vpr) break;
                float4 xv = __ldcs(xp + 32 * k);
                float4 cv = __ldg(cp + 32 * k);
                float d0 = xv.x - cv.x, d1 = xv.y - cv.y;
                float d2 = xv.z - cv.z, d3 = xv.w - cv.w;
                a0 = fmaf(d0, d0, a0); a1 = fmaf(d1, d1, a1);
                a2 = fmaf(d2, d2, a2); a3 = fmaf(d3, d3, a3);
            }
        }
    }

    // ---- CTA reduce ----
    float s = (a0 + a1) + (a2 + a3);
    #pragma unroll
    for (int o = 16; o; o >>= 1)
        s += __shfl_xor_sync(0xffffffffu, s, o);

    __shared__ float bsum[THREADS / 32];
    if (lane == 0) bsum[tid >> 5] = s;
    __syncthreads();

    // ---- last-block finalize (self-cleaning for graph replay) ----
    if (tid == 0) {
        float t = 0.f;
        #pragma unroll
        for (int w = 0; w < THREADS / 32; w++) t += bsum[w];
        atomicAdd(&g_acc, t);
        __threadfence();
        unsigned int ticket = atomicAdd(&g_cnt, 1u);
        if (ticket == gridDim.x - 1) {
            out[0] = g_acc * inv_B;
            g_acc = 0.0f;                      // restore state for next replay
            g_cnt = 0u;
            __threadfence();
        }
    }
}

extern "C" void kernel_launch(void* const* d_in, const int* in_sizes, int n_in,
                              void* d_out, int out_size) {
    const float* x       = (const float*)d_in[0];
    const void*  labels  = d_in[1];
    const float* centers = (const float*)d_in[2];
    float*       out     = (float*)d_out;

    const int B   = in_sizes[1];
    const int D   = in_sizes[0] / B;
    const int vpr = D >> 2;                   // float4 per row
    const int nunits = B * 4;                 // quarter-row units
    const float inv_B = 1.0f / (float)B;

    if (vpr == 512 && B >= 64) {
        center_loss_fused<512><<<NBLOCKS, THREADS>>>(
            (const float4*)x, (const unsigned int*)labels,
            (const float4*)centers, out, nunits, vpr, inv_B);
    } else {
        center_loss_fused<0><<<NBLOCKS, THREADS>>>(
            (const float4*)x, (const unsigned int*)labels,
            (const float4*)centers, out, nunits, vpr, inv_B);
    }
}